// round 16
// baseline (speedup 1.0000x reference)
#include <cuda_runtime.h>
#include <cuda_fp16.h>
#include <math_constants.h>

#define BATCH  2
#define COILS  16
#define NIM    256
#define KG     512
#define JW     6
#define TCENTER 3072
#define TLEN   6145
#define MPTS   409600
#define GSCALE   0x1p-34f
#define GSCALE_I 0x1p34f

#define PADI(i) ((i) + ((i) >> 5))
#define FFTBUF 536

#define NTILE 1024                  // 32x32 tiles of 16x16 cells
#define PB 64
#define CHUNKS_TOTAL (MPTS / PB)    // 6400
#define BLOCKS_X 148
#define CHUNKS_PER_BLOCK ((CHUNKS_TOTAL + BLOCKS_X - 1) / BLOCKS_X)   // 44

// Scratch
static __device__ __align__(256) float2  g_GrT[(size_t)BATCH*COILS*NIM*KG];
static __device__ __align__(256) __half2 g_Gft[(size_t)BATCH*KG*KG*COILS];
static __device__ int   g_hist[BATCH * NTILE];
static __device__ int   g_binoff[BATCH * NTILE];
static __device__ unsigned short g_tileid[(size_t)BATCH * MPTS];
static __device__ int   g_perm[(size_t)BATCH * MPTS];
static __device__ __align__(256) float g_tmp[(size_t)BATCH * MPTS * 32];

__device__ __forceinline__ float2 cmulf(float2 a, float2 b) {
    return make_float2(a.x*b.x - a.y*b.y, a.x*b.y + a.y*b.x);
}
__device__ __forceinline__ float clampq(float v) {
    return fminf(fmaxf(v, -60000.0f), 60000.0f);
}
__device__ __forceinline__ unsigned long long pk2(float lo, float hi) {
    unsigned long long r;
    asm("mov.b64 %0, {%1, %2};" : "=l"(r) : "f"(lo), "f"(hi));
    return r;
}
__device__ __forceinline__ void upk2(float& lo, float& hi, unsigned long long v) {
    asm("mov.b64 {%0, %1}, %2;" : "=f"(lo), "=f"(hi) : "l"(v));
}
__device__ __forceinline__ void fma2(unsigned long long& d,
                                     unsigned long long a,
                                     unsigned long long b) {
    asm("fma.rn.f32x2 %0, %1, %2, %0;" : "+l"(d) : "l"(a), "l"(b));
}

// ---------------------------------------------------------------------------
// 8-point DFTs (full + zero-padded half variant)
// ---------------------------------------------------------------------------
__device__ __forceinline__ void dft8_tail(float2 x[8],
                                          float2 E0, float2 E1, float2 E2, float2 E3,
                                          float2 O0, float2 O1, float2 O2, float2 O3) {
    const float RH = 0.70710678118654752f;
    float2 t1 = make_float2(RH * (O1.x + O1.y), RH * (O1.y - O1.x));
    float2 t2 = make_float2(O2.y, -O2.x);
    float2 t3 = make_float2(RH * (O3.y - O3.x), -RH * (O3.x + O3.y));
    x[0] = make_float2(E0.x + O0.x, E0.y + O0.y);
    x[4] = make_float2(E0.x - O0.x, E0.y - O0.y);
    x[1] = make_float2(E1.x + t1.x, E1.y + t1.y);
    x[5] = make_float2(E1.x - t1.x, E1.y - t1.y);
    x[2] = make_float2(E2.x + t2.x, E2.y + t2.y);
    x[6] = make_float2(E2.x - t2.x, E2.y - t2.y);
    x[3] = make_float2(E3.x + t3.x, E3.y + t3.y);
    x[7] = make_float2(E3.x - t3.x, E3.y - t3.y);
}

__device__ __forceinline__ void dft8(float2 x[8]) {
    float2 ec0 = make_float2(x[0].x + x[4].x, x[0].y + x[4].y);
    float2 ec1 = make_float2(x[0].x - x[4].x, x[0].y - x[4].y);
    float2 ec2 = make_float2(x[2].x + x[6].x, x[2].y + x[6].y);
    float2 ec3 = make_float2(x[2].x - x[6].x, x[2].y - x[6].y);
    float2 E0 = make_float2(ec0.x + ec2.x, ec0.y + ec2.y);
    float2 E2 = make_float2(ec0.x - ec2.x, ec0.y - ec2.y);
    float2 E1 = make_float2(ec1.x + ec3.y, ec1.y - ec3.x);
    float2 E3 = make_float2(ec1.x - ec3.y, ec1.y + ec3.x);
    float2 oc0 = make_float2(x[1].x + x[5].x, x[1].y + x[5].y);
    float2 oc1 = make_float2(x[1].x - x[5].x, x[1].y - x[5].y);
    float2 oc2 = make_float2(x[3].x + x[7].x, x[3].y + x[7].y);
    float2 oc3 = make_float2(x[3].x - x[7].x, x[3].y - x[7].y);
    float2 O0 = make_float2(oc0.x + oc2.x, oc0.y + oc2.y);
    float2 O2 = make_float2(oc0.x - oc2.x, oc0.y - oc2.y);
    float2 O1 = make_float2(oc1.x + oc3.y, oc1.y - oc3.x);
    float2 O3 = make_float2(oc1.x - oc3.y, oc1.y + oc3.x);
    dft8_tail(x, E0, E1, E2, E3, O0, O1, O2, O3);
}

__device__ __forceinline__ void dft8_half(float2 x[8]) {
    float2 a = x[0], b = x[1], c = x[2], d = x[3];
    float2 E0 = make_float2(a.x + c.x, a.y + c.y);
    float2 E2 = make_float2(a.x - c.x, a.y - c.y);
    float2 E1 = make_float2(a.x + c.y, a.y - c.x);
    float2 E3 = make_float2(a.x - c.y, a.y + c.x);
    float2 O0 = make_float2(b.x + d.x, b.y + d.y);
    float2 O2 = make_float2(b.x - d.x, b.y - d.y);
    float2 O1 = make_float2(b.x + d.y, b.y - d.x);
    float2 O3 = make_float2(b.x - d.y, b.y + d.x);
    dft8_tail(x, E0, E1, E2, E3, O0, O1, O2, O3);
}

__device__ __forceinline__ void fft512_r8_reg(float2 x[8], float* re, float* im,
                                              const float2* tw512, int tt) {
    {
        int base = 8 * tt;
#pragma unroll
        for (int i = 0; i < 8; i++) {
            int a = PADI(base + i);
            re[a] = x[i].x; im[a] = x[i].y;
        }
    }
    __syncthreads();
    {
        int g = tt & 7, r = tt >> 3;
        int base = 64 * g + r;
#pragma unroll
        for (int i = 0; i < 8; i++) {
            int a = PADI(base + 8 * i);
            x[i] = make_float2(re[a], im[a]);
        }
#pragma unroll
        for (int i = 1; i < 8; i++)
            x[i] = cmulf(x[i], tw512[(8 * r * i) & 511]);
        dft8(x);
#pragma unroll
        for (int i = 0; i < 8; i++) {
            int a = PADI(base + 8 * i);
            re[a] = x[i].x; im[a] = x[i].y;
        }
    }
    __syncthreads();
    {
#pragma unroll
        for (int i = 0; i < 8; i++) {
            int a = PADI(tt + 64 * i);
            x[i] = make_float2(re[a], im[a]);
        }
#pragma unroll
        for (int i = 1; i < 8; i++)
            x[i] = cmulf(x[i], tw512[(tt * i) & 511]);
        dft8(x);
#pragma unroll
        for (int i = 0; i < 8; i++) {
            int a = PADI(tt + 64 * i);
            re[a] = x[i].x; im[a] = x[i].y;
        }
    }
    __syncthreads();
}

__device__ __forceinline__ int s1_base(int tt) {
    return 8 * (tt & 7) + (tt >> 3);
}

// ---------------------------------------------------------------------------
// Pass 1: apodize + row FFT + transposed store (as R14).
// ---------------------------------------------------------------------------
__global__ __launch_bounds__(256) void pass1_rowfft(const float* __restrict__ x,
                                                    const float* __restrict__ sc) {
    __shared__ float  s_re[4][FFTBUF];
    __shared__ float  s_im[4][FFTBUF];
    __shared__ float2 tw512[512];
    int tid = threadIdx.x;
    int f   = tid >> 6;
    int tt  = tid & 63;
    int r0  = blockIdx.x * 4;
    int r   = r0 + f;
    int bc  = blockIdx.y;

#pragma unroll
    for (int j = 0; j < 2; j++) {
        int idx = tid + 256 * j;
        float ang = -CUDART_PI_F * (float)idx / 256.0f;
        float s, c; sincosf(ang, &s, &c);
        tw512[idx] = make_float2(c, s);
    }

    float* re = s_re[f];
    float* im = s_im[f];

    const float* xr  = x  + ((size_t)bc * 2 + 0) * (NIM * NIM) + (size_t)r * NIM;
    const float* xi  = x  + ((size_t)bc * 2 + 1) * (NIM * NIM) + (size_t)r * NIM;
    const float* scr = sc + (size_t)r * NIM;
    const float* sci = sc + (size_t)NIM * NIM + (size_t)r * NIM;

    float2 xv[8];
    int nb = s1_base(tt);
#pragma unroll
    for (int i = 0; i < 4; i++) {
        int n = i * 64 + nb;
        float a = xr[n], b = xi[n], cr = scr[n], ci = sci[n];
        xv[i] = make_float2(a * cr - b * ci, a * ci + b * cr);
    }
    dft8_half(xv);
    __syncthreads();

    fft512_r8_reg(xv, re, im, tw512, tt);

    float2* outT = g_GrT + (size_t)bc * NIM * KG;
#pragma unroll
    for (int j = 0; j < 8; j++) {
        int idx = j * 256 + tid;
        int col = idx >> 2;
        int r4  = idx & 3;
        int d   = PADI(col);
        outT[(size_t)col * NIM + r0 + r4] = make_float2(s_re[r4][d], s_im[r4][d]);
    }
}

// ---------------------------------------------------------------------------
// Pass 2: column FFT, staged coalesced fp16 write (as R14).
// ---------------------------------------------------------------------------
#define P2_SMEM (4 * FFTBUF * 2 * 4 + 512 * 8 + 512 * 17 * 4)
__global__ __launch_bounds__(256) void pass2_colfft() {
    extern __shared__ char smem2[];
    float*   s_re  = (float*)smem2;
    float*   s_im  = s_re + 4 * FFTBUF;
    float2*  tw512 = (float2*)(s_im + 4 * FFTBUF);
    __half2* stage = (__half2*)(tw512 + 512);

    int tid = threadIdx.x;
    int f   = tid >> 6;
    int tt  = tid & 63;
    int col = blockIdx.x;
    int b   = blockIdx.y;

#pragma unroll
    for (int j = 0; j < 2; j++) {
        int idx = tid + 256 * j;
        float ang = -CUDART_PI_F * (float)idx / 256.0f;
        float s, cc; sincosf(ang, &s, &cc);
        tw512[idx] = make_float2(cc, s);
    }
    __syncthreads();

    float* re = s_re + f * FFTBUF;
    float* im = s_im + f * FFTBUF;
    int nb = s1_base(tt);

#pragma unroll 1
    for (int cc = 0; cc < 4; cc++) {
        int c = cc * 4 + f;
        const float2* inT = g_GrT + ((size_t)(b * COILS + c) * NIM) * KG
                          + (size_t)col * NIM;
        float2 xv[8];
#pragma unroll
        for (int i = 0; i < 4; i++)
            xv[i] = inT[i * 64 + nb];
        dft8_half(xv);

        fft512_r8_reg(xv, re, im, tw512, tt);

#pragma unroll
        for (int j = 0; j < 8; j++) {
            int n = tt + 64 * j;
            int d = PADI(n);
            stage[n * 17 + c] =
                __floats2half2_rn(clampq(re[d] * GSCALE), clampq(im[d] * GSCALE));
        }
        __syncthreads();
    }

    __half2* out = g_Gft + (size_t)b * KG * KG * COILS + (size_t)col * COILS;
#pragma unroll
    for (int i = 0; i < 32; i++) {
        int idx = i * 256 + tid;
        int n   = idx >> 4;
        int c   = idx & 15;
        out[(size_t)n * (KG * COILS) + c] = stage[n * 17 + c];
    }
}

// ---------------------------------------------------------------------------
// Counting sort by 16x16-cell tile
// ---------------------------------------------------------------------------
__global__ __launch_bounds__(1024) void zero_hist() {
    int t = threadIdx.x;
    g_hist[t] = 0;
    g_hist[t + 1024] = 0;
}

__global__ __launch_bounds__(256) void sortA(const float* __restrict__ om) {
    int b = blockIdx.y;
    int m = blockIdx.x * 256 + threadIdx.x;
    float om0 = om[((size_t)b * 2 + 0) * MPTS + m];
    float om1 = om[((size_t)b * 2 + 1) * MPTS + m];
    const float S = (float)(KG / (2.0 * 3.14159265358979323846));
    int r0 = ((int)floorf(om0 * S)) & (KG - 1);
    int c0 = ((int)floorf(om1 * S)) & (KG - 1);
    int tile = (r0 >> 4) * 32 + (c0 >> 4);
    g_tileid[(size_t)b * MPTS + m] = (unsigned short)tile;
    atomicAdd(&g_hist[b * NTILE + tile], 1);
}

__global__ __launch_bounds__(1024) void scan_kernel() {
    __shared__ int warpsum[32];
    int t = threadIdx.x;
    int lane = t & 31, w = t >> 5;
#pragma unroll 1
    for (int b = 0; b < BATCH; b++) {
        int v = g_hist[b * NTILE + t];
        int x = v;
#pragma unroll
        for (int off = 1; off < 32; off <<= 1) {
            int y = __shfl_up_sync(0xFFFFFFFFu, x, off);
            if (lane >= off) x += y;
        }
        if (lane == 31) warpsum[w] = x;
        __syncthreads();
        if (w == 0) {
            int s = warpsum[lane];
#pragma unroll
            for (int off = 1; off < 32; off <<= 1) {
                int y = __shfl_up_sync(0xFFFFFFFFu, s, off);
                if (lane >= off) s += y;
            }
            warpsum[lane] = s;
        }
        __syncthreads();
        int incl = x + (w > 0 ? warpsum[w - 1] : 0);
        g_binoff[b * NTILE + t] = incl - v;   // exclusive
        __syncthreads();
    }
}

__global__ __launch_bounds__(256) void sortB() {
    int b = blockIdx.y;
    int m = blockIdx.x * 256 + threadIdx.x;
    int tile = g_tileid[(size_t)b * MPTS + m];
    int pos  = atomicAdd(&g_binoff[b * NTILE + tile], 1);
    g_perm[(size_t)b * MPTS + pos] = m;
}

// ---------------------------------------------------------------------------
// PERSISTENT sorted interpolation: grid (148, BATCH) -> 2 blocks/SM.
// Each block sweeps a CONTIGUOUS range of sorted 64-point chunks, so its
// gather working set is 1-2 tiles (~31-62KB) and stays L1-resident.
// Results stored as per-point 128B records in g_tmp (4 full sectors/point).
// ---------------------------------------------------------------------------
__global__ __launch_bounds__(256) void interp_sorted(const float* __restrict__ om,
                                                     const float* __restrict__ tab0,
                                                     const float* __restrict__ tab1,
                                                     const float* __restrict__ nshift) {
    __shared__ float2 sc0[PB][JW];
    __shared__ float2 sc1[PB][JW];
    __shared__ int    si0[PB][JW];
    __shared__ int    si1[PB][JW];
    __shared__ float2 sph[PB];
    __shared__ int    sm_m[PB];

    int b  = blockIdx.y;
    int t  = threadIdx.x;
    int c0 = blockIdx.x * CHUNKS_PER_BLOCK;
    int c1 = c0 + CHUNKS_PER_BLOCK;
    if (c1 > CHUNKS_TOTAL) c1 = CHUNKS_TOTAL;

    int p  = t >> 2;
    int q4 = (t & 3) * 4;
    const __half2* G = g_Gft + (size_t)b * KG * KG * COILS + q4;

#pragma unroll 1
    for (int ch = c0; ch < c1; ch++) {
        int s0 = ch * PB;
        if (t < PB) {
            int m = g_perm[(size_t)b * MPTS + s0 + t];
            sm_m[t] = m;
            float om0 = om[((size_t)b * 2 + 0) * MPTS + m];
            float om1 = om[((size_t)b * 2 + 1) * MPTS + m];
            const float S = (float)(KG / (2.0 * 3.14159265358979323846));
            float tm0 = om0 * S;
            float tm1 = om1 * S;
            int koff0 = (int)floorf(tm0 - 3.0f) + 1;
            int koff1 = (int)floorf(tm1 - 3.0f) + 1;
#pragma unroll
            for (int j = 0; j < JW; j++) {
                int g0   = koff0 + j;
                int idx0 = __float2int_rn((tm0 - (float)g0) * 1024.0f) + TCENTER;
                sc0[t][j] = make_float2(tab0[idx0], tab0[TLEN + idx0]);
                si0[t][j] = (g0 & (KG - 1)) * (KG * COILS);
                int g1   = koff1 + j;
                int idx1 = __float2int_rn((tm1 - (float)g1) * 1024.0f) + TCENTER;
                sc1[t][j] = make_float2(tab1[idx1], tab1[TLEN + idx1]);
                si1[t][j] = (g1 & (KG - 1)) * COILS;
            }
            float ph = om0 * nshift[0] + om1 * nshift[1];
            float sp, cp;
            sincosf(ph, &sp, &cp);
            sph[t] = make_float2(cp * GSCALE_I, sp * GSCALE_I);
        }
        __syncthreads();

        float2 rc1[JW];
        int    ri1[JW];
#pragma unroll
        for (int j = 0; j < JW; j++) {
            rc1[j] = sc1[p][j];
            ri1[j] = si1[p][j];
        }

        unsigned long long acc0 = pk2(0.f, 0.f);
        unsigned long long acc1 = acc0, acc2 = acc0, acc3 = acc0;

#pragma unroll
        for (int a = 0; a < JW; a++) {
            float2 ca   = sc0[p][a];
            int    roff = si0[p][a];
#pragma unroll
            for (int g = 0; g < 2; g++) {
                float4 raw0 = *reinterpret_cast<const float4*>(G + roff + ri1[g * 3 + 0]);
                float4 raw1 = *reinterpret_cast<const float4*>(G + roff + ri1[g * 3 + 1]);
                float4 raw2 = *reinterpret_cast<const float4*>(G + roff + ri1[g * 3 + 2]);
#pragma unroll
                for (int u = 0; u < 3; u++) {
                    float4 raw = (u == 0) ? raw0 : (u == 1) ? raw1 : raw2;
                    float2 cf  = cmulf(ca, rc1[g * 3 + u]);
                    unsigned long long cxx = pk2(cf.x, cf.x);
                    unsigned long long cyn = pk2(-cf.y, cf.y);
                    float2 v0 = __half22float2(*reinterpret_cast<__half2*>(&raw.x));
                    float2 v1 = __half22float2(*reinterpret_cast<__half2*>(&raw.y));
                    float2 v2 = __half22float2(*reinterpret_cast<__half2*>(&raw.z));
                    float2 v3 = __half22float2(*reinterpret_cast<__half2*>(&raw.w));
                    fma2(acc0, pk2(v0.x, v0.y), cxx);
                    fma2(acc0, pk2(v0.y, v0.x), cyn);
                    fma2(acc1, pk2(v1.x, v1.y), cxx);
                    fma2(acc1, pk2(v1.y, v1.x), cyn);
                    fma2(acc2, pk2(v2.x, v2.y), cxx);
                    fma2(acc2, pk2(v2.y, v2.x), cyn);
                    fma2(acc3, pk2(v3.x, v3.y), cxx);
                    fma2(acc3, pk2(v3.y, v3.x), cyn);
                }
            }
        }

        float2 a0, a1, a2, a3;
        upk2(a0.x, a0.y, acc0);
        upk2(a1.x, a1.y, acc1);
        upk2(a2.x, a2.y, acc2);
        upk2(a3.x, a3.y, acc3);

        float2 ph = sph[p];
        // 128B record per point: float2[coil] = (re, im)
        float2* rec = reinterpret_cast<float2*>(
            g_tmp + ((size_t)b * MPTS + sm_m[p]) * 32) + q4;
        rec[0] = cmulf(a0, ph);
        rec[1] = cmulf(a1, ph);
        rec[2] = cmulf(a2, ph);
        rec[3] = cmulf(a3, ph);
        __syncthreads();   // smem reuse next chunk
    }
}

// ---------------------------------------------------------------------------
// Final layout: g_tmp (B, M, 32) -> out (B, 32, M), tiled via smem.
// ---------------------------------------------------------------------------
__global__ __launch_bounds__(256) void transpose_out(float* __restrict__ out) {
    __shared__ float s[64 * 33];
    int b  = blockIdx.y;
    int m0 = blockIdx.x * 64;
    int t  = threadIdx.x;

    const float* tmp = g_tmp + ((size_t)b * MPTS + m0) * 32;
#pragma unroll
    for (int i = 0; i < 8; i++) {
        int idx = i * 256 + t;
        int ml  = idx >> 5;
        int cr  = idx & 31;
        s[ml * 33 + cr] = tmp[idx];
    }
    __syncthreads();

    float* outp = out + (size_t)b * 32 * MPTS + m0;
#pragma unroll
    for (int i = 0; i < 8; i++) {
        int idx = i * 256 + t;
        int cr  = idx >> 6;
        int ml  = idx & 63;
        outp[(size_t)cr * MPTS + ml] = s[ml * 33 + cr];
    }
}

extern "C" void kernel_launch(void* const* d_in, const int* in_sizes, int n_in,
                              void* d_out, int out_size) {
    (void)in_sizes; (void)n_in; (void)out_size;
    const float* x      = (const float*)d_in[0];
    const float* om     = (const float*)d_in[1];
    const float* sc     = (const float*)d_in[2];
    const float* tab0   = (const float*)d_in[3];
    const float* tab1   = (const float*)d_in[4];
    const float* nshift = (const float*)d_in[5];
    float* out          = (float*)d_out;

    cudaFuncSetAttribute(pass2_colfft,
                         cudaFuncAttributeMaxDynamicSharedMemorySize, P2_SMEM);

    zero_hist<<<1, 1024>>>();
    sortA<<<dim3(MPTS / 256, BATCH), 256>>>(om);

    dim3 g1(NIM / 4, BATCH * COILS);
    pass1_rowfft<<<g1, 256>>>(x, sc);

    scan_kernel<<<1, 1024>>>();
    sortB<<<dim3(MPTS / 256, BATCH), 256>>>();

    dim3 g2(KG, BATCH);
    pass2_colfft<<<g2, 256, P2_SMEM>>>();

    interp_sorted<<<dim3(BLOCKS_X, BATCH), 256>>>(om, tab0, tab1, nshift);
    transpose_out<<<dim3(MPTS / 64, BATCH), 256>>>(out);
}

// round 17
// speedup vs baseline: 1.9137x; 1.9137x over previous
#include <cuda_runtime.h>
#include <cuda_fp16.h>
#include <math_constants.h>

#define BATCH  2
#define COILS  16
#define NIM    256
#define KG     512
#define JW     6
#define TCENTER 3072
#define TLEN   6145
#define MPTS   409600
#define GSCALE   0x1p-34f
#define GSCALE_I 0x1p34f

#define PADI(i) ((i) + ((i) >> 5))   // bank-conflict padding
#define FFTBUF 536

// Scratch: TRANSPOSED row-FFT output (B,C, col*256+row) fp32 and
// coil-innermost grid (B, 512*512, C) fp16
static __device__ __align__(256) float2  g_GrT[(size_t)BATCH*COILS*NIM*KG];
static __device__ __align__(256) __half2 g_Gft[(size_t)BATCH*KG*KG*COILS];

__device__ __forceinline__ float2 cmulf(float2 a, float2 b) {
    return make_float2(a.x*b.x - a.y*b.y, a.x*b.y + a.y*b.x);
}

__device__ __forceinline__ float clampq(float v) {
    return fminf(fmaxf(v, -60000.0f), 60000.0f);
}

// ---- packed f32x2 helpers (sm_103a) ----
__device__ __forceinline__ unsigned long long pk2(float lo, float hi) {
    unsigned long long r;
    asm("mov.b64 %0, {%1, %2};" : "=l"(r) : "f"(lo), "f"(hi));
    return r;
}
__device__ __forceinline__ void upk2(float& lo, float& hi, unsigned long long v) {
    asm("mov.b64 {%0, %1}, %2;" : "=f"(lo), "=f"(hi) : "l"(v));
}
__device__ __forceinline__ void fma2(unsigned long long& d,
                                     unsigned long long a,
                                     unsigned long long b) {
    asm("fma.rn.f32x2 %0, %1, %2, %0;" : "+l"(d) : "l"(a), "l"(b));
}

// ---------------------------------------------------------------------------
// 8-point DFTs. dft8: full. dft8_half: x[4..7] == 0 (zero-pad fast path).
// ---------------------------------------------------------------------------
__device__ __forceinline__ void dft8_tail(float2 x[8],
                                          float2 E0, float2 E1, float2 E2, float2 E3,
                                          float2 O0, float2 O1, float2 O2, float2 O3) {
    const float RH = 0.70710678118654752f;
    float2 t1 = make_float2(RH * (O1.x + O1.y), RH * (O1.y - O1.x));
    float2 t2 = make_float2(O2.y, -O2.x);
    float2 t3 = make_float2(RH * (O3.y - O3.x), -RH * (O3.x + O3.y));
    x[0] = make_float2(E0.x + O0.x, E0.y + O0.y);
    x[4] = make_float2(E0.x - O0.x, E0.y - O0.y);
    x[1] = make_float2(E1.x + t1.x, E1.y + t1.y);
    x[5] = make_float2(E1.x - t1.x, E1.y - t1.y);
    x[2] = make_float2(E2.x + t2.x, E2.y + t2.y);
    x[6] = make_float2(E2.x - t2.x, E2.y - t2.y);
    x[3] = make_float2(E3.x + t3.x, E3.y + t3.y);
    x[7] = make_float2(E3.x - t3.x, E3.y - t3.y);
}

__device__ __forceinline__ void dft8(float2 x[8]) {
    float2 ec0 = make_float2(x[0].x + x[4].x, x[0].y + x[4].y);
    float2 ec1 = make_float2(x[0].x - x[4].x, x[0].y - x[4].y);
    float2 ec2 = make_float2(x[2].x + x[6].x, x[2].y + x[6].y);
    float2 ec3 = make_float2(x[2].x - x[6].x, x[2].y - x[6].y);
    float2 E0 = make_float2(ec0.x + ec2.x, ec0.y + ec2.y);
    float2 E2 = make_float2(ec0.x - ec2.x, ec0.y - ec2.y);
    float2 E1 = make_float2(ec1.x + ec3.y, ec1.y - ec3.x);
    float2 E3 = make_float2(ec1.x - ec3.y, ec1.y + ec3.x);
    float2 oc0 = make_float2(x[1].x + x[5].x, x[1].y + x[5].y);
    float2 oc1 = make_float2(x[1].x - x[5].x, x[1].y - x[5].y);
    float2 oc2 = make_float2(x[3].x + x[7].x, x[3].y + x[7].y);
    float2 oc3 = make_float2(x[3].x - x[7].x, x[3].y - x[7].y);
    float2 O0 = make_float2(oc0.x + oc2.x, oc0.y + oc2.y);
    float2 O2 = make_float2(oc0.x - oc2.x, oc0.y - oc2.y);
    float2 O1 = make_float2(oc1.x + oc3.y, oc1.y - oc3.x);
    float2 O3 = make_float2(oc1.x - oc3.y, oc1.y + oc3.x);
    dft8_tail(x, E0, E1, E2, E3, O0, O1, O2, O3);
}

__device__ __forceinline__ void dft8_half(float2 x[8]) {
    float2 a = x[0], b = x[1], c = x[2], d = x[3];
    float2 E0 = make_float2(a.x + c.x, a.y + c.y);
    float2 E2 = make_float2(a.x - c.x, a.y - c.y);
    float2 E1 = make_float2(a.x + c.y, a.y - c.x);
    float2 E3 = make_float2(a.x - c.y, a.y + c.x);
    float2 O0 = make_float2(b.x + d.x, b.y + d.y);
    float2 O2 = make_float2(b.x - d.x, b.y - d.y);
    float2 O1 = make_float2(b.x + d.y, b.y - d.x);
    float2 O3 = make_float2(b.x - d.y, b.y + d.x);
    dft8_tail(x, E0, E1, E2, E3, O0, O1, O2, O3);
}

// ---------------------------------------------------------------------------
// 512-pt FFT: stage 1 in registers (caller used dft8_half), stages 2-3 in smem.
// ---------------------------------------------------------------------------
__device__ __forceinline__ void fft512_r8_reg(float2 x[8], float* re, float* im,
                                              const float2* tw512, int tt) {
    {
        int base = 8 * tt;
#pragma unroll
        for (int i = 0; i < 8; i++) {
            int a = PADI(base + i);
            re[a] = x[i].x; im[a] = x[i].y;
        }
    }
    __syncthreads();
    {
        int g = tt & 7, r = tt >> 3;
        int base = 64 * g + r;
#pragma unroll
        for (int i = 0; i < 8; i++) {
            int a = PADI(base + 8 * i);
            x[i] = make_float2(re[a], im[a]);
        }
#pragma unroll
        for (int i = 1; i < 8; i++)
            x[i] = cmulf(x[i], tw512[(8 * r * i) & 511]);
        dft8(x);
#pragma unroll
        for (int i = 0; i < 8; i++) {
            int a = PADI(base + 8 * i);
            re[a] = x[i].x; im[a] = x[i].y;
        }
    }
    __syncthreads();
    {
#pragma unroll
        for (int i = 0; i < 8; i++) {
            int a = PADI(tt + 64 * i);
            x[i] = make_float2(re[a], im[a]);
        }
#pragma unroll
        for (int i = 1; i < 8; i++)
            x[i] = cmulf(x[i], tw512[(tt * i) & 511]);
        dft8(x);
#pragma unroll
        for (int i = 0; i < 8; i++) {
            int a = PADI(tt + 64 * i);
            re[a] = x[i].x; im[a] = x[i].y;
        }
    }
    __syncthreads();
}

__device__ __forceinline__ int s1_base(int tt) {
    return 8 * (tt & 7) + (tt >> 3);
}

// ---------------------------------------------------------------------------
// Pass 1: apodize + row FFT + TRANSPOSED store. 4 rows per 256-thread block.
// ---------------------------------------------------------------------------
__global__ __launch_bounds__(256) void pass1_rowfft(const float* __restrict__ x,
                                                    const float* __restrict__ sc) {
    __shared__ float  s_re[4][FFTBUF];
    __shared__ float  s_im[4][FFTBUF];
    __shared__ float2 tw512[512];
    int tid = threadIdx.x;
    int f   = tid >> 6;
    int tt  = tid & 63;
    int r0  = blockIdx.x * 4;
    int r   = r0 + f;
    int bc  = blockIdx.y;

#pragma unroll
    for (int j = 0; j < 2; j++) {
        int idx = tid + 256 * j;
        float ang = -CUDART_PI_F * (float)idx / 256.0f;
        float s, c; sincosf(ang, &s, &c);
        tw512[idx] = make_float2(c, s);
    }

    float* re = s_re[f];
    float* im = s_im[f];

    const float* xr  = x  + ((size_t)bc * 2 + 0) * (NIM * NIM) + (size_t)r * NIM;
    const float* xi  = x  + ((size_t)bc * 2 + 1) * (NIM * NIM) + (size_t)r * NIM;
    const float* scr = sc + (size_t)r * NIM;
    const float* sci = sc + (size_t)NIM * NIM + (size_t)r * NIM;

    float2 xv[8];
    int nb = s1_base(tt);
#pragma unroll
    for (int i = 0; i < 4; i++) {
        int n = i * 64 + nb;
        float a = xr[n], b = xi[n], cr = scr[n], ci = sci[n];
        xv[i] = make_float2(a * cr - b * ci, a * ci + b * cr);
    }
    dft8_half(xv);
    __syncthreads();   // tw512 ready

    fft512_r8_reg(xv, re, im, tw512, tt);

    float2* outT = g_GrT + (size_t)bc * NIM * KG;
#pragma unroll
    for (int j = 0; j < 8; j++) {
        int idx = j * 256 + tid;
        int col = idx >> 2;
        int r4  = idx & 3;
        int d   = PADI(col);
        outT[(size_t)col * NIM + r0 + r4] = make_float2(s_re[r4][d], s_im[r4][d]);
    }
}

// ---------------------------------------------------------------------------
// Pass 2: column FFT for ALL 16 coils of one column per block, staged in smem,
// then one fully-coalesced fp16 write phase. grid(KG, BATCH), 256 threads.
// ---------------------------------------------------------------------------
#define P2_SMEM (4 * FFTBUF * 2 * 4 + 512 * 8 + 512 * 17 * 4)
__global__ __launch_bounds__(256) void pass2_colfft() {
    extern __shared__ char smem2[];
    float*   s_re  = (float*)smem2;
    float*   s_im  = s_re + 4 * FFTBUF;
    float2*  tw512 = (float2*)(s_im + 4 * FFTBUF);
    __half2* stage = (__half2*)(tw512 + 512);

    int tid = threadIdx.x;
    int f   = tid >> 6;
    int tt  = tid & 63;
    int col = blockIdx.x;
    int b   = blockIdx.y;

#pragma unroll
    for (int j = 0; j < 2; j++) {
        int idx = tid + 256 * j;
        float ang = -CUDART_PI_F * (float)idx / 256.0f;
        float s, cc; sincosf(ang, &s, &cc);
        tw512[idx] = make_float2(cc, s);
    }
    __syncthreads();

    float* re = s_re + f * FFTBUF;
    float* im = s_im + f * FFTBUF;
    int nb = s1_base(tt);

#pragma unroll 1
    for (int cc = 0; cc < 4; cc++) {
        int c = cc * 4 + f;
        const float2* inT = g_GrT + ((size_t)(b * COILS + c) * NIM) * KG
                          + (size_t)col * NIM;
        float2 xv[8];
#pragma unroll
        for (int i = 0; i < 4; i++)
            xv[i] = inT[i * 64 + nb];
        dft8_half(xv);

        fft512_r8_reg(xv, re, im, tw512, tt);

#pragma unroll
        for (int j = 0; j < 8; j++) {
            int n = tt + 64 * j;
            int d = PADI(n);
            stage[n * 17 + c] =
                __floats2half2_rn(clampq(re[d] * GSCALE), clampq(im[d] * GSCALE));
        }
        __syncthreads();
    }

    __half2* out = g_Gft + (size_t)b * KG * KG * COILS + (size_t)col * COILS;
#pragma unroll
    for (int i = 0; i < 32; i++) {
        int idx = i * 256 + tid;
        int n   = idx >> 4;
        int c   = idx & 15;
        out[(size_t)n * (KG * COILS) + c] = stage[n * 17 + c];
    }
}

// ---------------------------------------------------------------------------
// Interpolation: 64 points x 4 threads (4 coils each) per block. grid(M/64, B).
// Packed f32x2 FMA accumulation + 6-deep load batching + direct stores.
// ---------------------------------------------------------------------------
#define PB 64
__global__ __launch_bounds__(256) void interp_kernel(const float* __restrict__ om,
                                                     const float* __restrict__ tab0,
                                                     const float* __restrict__ tab1,
                                                     const float* __restrict__ nshift,
                                                     float* __restrict__ out) {
    __shared__ float2 sc0[PB][JW];
    __shared__ float2 sc1[PB][JW];
    __shared__ int    si0[PB][JW];   // row * KG * COILS
    __shared__ int    si1[PB][JW];   // col * COILS
    __shared__ float2 sph[PB];

    int b  = blockIdx.y;
    int m0 = blockIdx.x * PB;
    int t  = threadIdx.x;

    if (t < PB) {
        int m = m0 + t;
        float om0 = om[((size_t)b * 2 + 0) * MPTS + m];
        float om1 = om[((size_t)b * 2 + 1) * MPTS + m];
        const float S = (float)(KG / (2.0 * 3.14159265358979323846));
        float tm0 = om0 * S;
        float tm1 = om1 * S;
        int koff0 = (int)floorf(tm0 - 3.0f) + 1;
        int koff1 = (int)floorf(tm1 - 3.0f) + 1;
#pragma unroll
        for (int j = 0; j < JW; j++) {
            int g0   = koff0 + j;
            int idx0 = __float2int_rn((tm0 - (float)g0) * 1024.0f) + TCENTER;
            sc0[t][j] = make_float2(tab0[idx0], tab0[TLEN + idx0]);
            si0[t][j] = (g0 & (KG - 1)) * (KG * COILS);
            int g1   = koff1 + j;
            int idx1 = __float2int_rn((tm1 - (float)g1) * 1024.0f) + TCENTER;
            sc1[t][j] = make_float2(tab1[idx1], tab1[TLEN + idx1]);
            si1[t][j] = (g1 & (KG - 1)) * COILS;
        }
        float ph = om0 * nshift[0] + om1 * nshift[1];
        float sp, cp;
        sincosf(ph, &sp, &cp);
        sph[t] = make_float2(cp * GSCALE_I, sp * GSCALE_I);
    }
    __syncthreads();

    int p  = t >> 2;
    int q4 = (t & 3) * 4;   // coil base (4 coils per thread)
    const __half2* G = g_Gft + (size_t)b * KG * KG * COILS + q4;

    // hoist column coefficients/offsets to registers
    float2 rc1[JW];
    int    ri1[JW];
#pragma unroll
    for (int j = 0; j < JW; j++) {
        rc1[j] = sc1[p][j];
        ri1[j] = si1[p][j];
    }

    unsigned long long acc0 = pk2(0.f, 0.f);
    unsigned long long acc1 = acc0, acc2 = acc0, acc3 = acc0;

#pragma unroll
    for (int a = 0; a < JW; a++) {
        float2 ca   = sc0[p][a];
        int    roff = si0[p][a];
        // batch ALL 6 neighbor loads of this row (MLP=6)
        float4 raw[JW];
#pragma unroll
        for (int u = 0; u < JW; u++)
            raw[u] = *reinterpret_cast<const float4*>(G + roff + ri1[u]);
#pragma unroll
        for (int u = 0; u < JW; u++) {
            float2 cf  = cmulf(ca, rc1[u]);
            unsigned long long cxx = pk2(cf.x, cf.x);
            unsigned long long cyn = pk2(-cf.y, cf.y);
            float2 v0 = __half22float2(*reinterpret_cast<__half2*>(&raw[u].x));
            float2 v1 = __half22float2(*reinterpret_cast<__half2*>(&raw[u].y));
            float2 v2 = __half22float2(*reinterpret_cast<__half2*>(&raw[u].z));
            float2 v3 = __half22float2(*reinterpret_cast<__half2*>(&raw[u].w));
            fma2(acc0, pk2(v0.x, v0.y), cxx);
            fma2(acc0, pk2(v0.y, v0.x), cyn);
            fma2(acc1, pk2(v1.x, v1.y), cxx);
            fma2(acc1, pk2(v1.y, v1.x), cyn);
            fma2(acc2, pk2(v2.x, v2.y), cxx);
            fma2(acc2, pk2(v2.y, v2.x), cyn);
            fma2(acc3, pk2(v3.x, v3.y), cxx);
            fma2(acc3, pk2(v3.y, v3.x), cyn);
        }
    }

    float2 a0, a1, a2, a3;
    upk2(a0.x, a0.y, acc0);
    upk2(a1.x, a1.y, acc1);
    upk2(a2.x, a2.y, acc2);
    upk2(a3.x, a3.y, acc3);

    float2 ph = sph[p];
    float2 r0 = cmulf(a0, ph);
    float2 r1 = cmulf(a1, ph);
    float2 r2 = cmulf(a2, ph);
    float2 r3 = cmulf(a3, ph);

    // Direct stores: lanes with equal (t&3) hit 8 consecutive floats -> full
    // 32B sectors, 4 plane-groups per STG instruction.
    float* outp = out + ((size_t)(b * COILS + q4) * 2) * MPTS + m0 + p;
    outp[0]        = r0.x;  outp[MPTS]     = r0.y;
    outp += 2 * MPTS;
    outp[0]        = r1.x;  outp[MPTS]     = r1.y;
    outp += 2 * MPTS;
    outp[0]        = r2.x;  outp[MPTS]     = r2.y;
    outp += 2 * MPTS;
    outp[0]        = r3.x;  outp[MPTS]     = r3.y;
}

extern "C" void kernel_launch(void* const* d_in, const int* in_sizes, int n_in,
                              void* d_out, int out_size) {
    (void)in_sizes; (void)n_in; (void)out_size;
    const float* x      = (const float*)d_in[0];
    const float* om     = (const float*)d_in[1];
    const float* sc     = (const float*)d_in[2];
    const float* tab0   = (const float*)d_in[3];
    const float* tab1   = (const float*)d_in[4];
    const float* nshift = (const float*)d_in[5];
    float* out          = (float*)d_out;

    cudaFuncSetAttribute(pass2_colfft,
                         cudaFuncAttributeMaxDynamicSharedMemorySize, P2_SMEM);

    dim3 g1(NIM / 4, BATCH * COILS);
    pass1_rowfft<<<g1, 256>>>(x, sc);

    dim3 g2(KG, BATCH);
    pass2_colfft<<<g2, 256, P2_SMEM>>>();

    dim3 g3(MPTS / PB, BATCH);
    interp_kernel<<<g3, 256>>>(om, tab0, tab1, nshift, out);
}